// round 1
// baseline (speedup 1.0000x reference)
#include <cuda_runtime.h>
#include <cstdint>
#include <cstddef>

#define B_SZ  256
#define C_SZ  10
#define N_CAP 1152
#define DIN   8
#define U_SZ  16
#define ROW   18   // padded floats per u_hat row in K2 smem

// 189 MB scratch for u_hat[b][c][n][u] (fp32). Static __device__ array:
// the sanctioned no-allocation path for scratch.
__device__ float g_uhat[(size_t)B_SZ * C_SZ * N_CAP * U_SZ];

// Packed fp32x2 FMA (sm_100+): d = a*b + c lanewise on two packed f32.
#define FFMA2(d, a, bb, cc) \
    asm("fma.rn.f32x2 %0, %1, %2, %3;" : "=l"(d) : "l"(a), "l"(bb), "l"(cc))

// ---------------------------------------------------------------------------
// K1: u_hat[b,c,n,u] = sum_i x[b,n,i] * W[c,n,i,u]
// Grid: (N/32, C). Block: 256 threads = 8 b-lanes x 32 n-lanes.
// W tile (32 n x 128) staged in smem (padded rows of 132 floats -> no LDS
// conflicts on the 16B reads). x read straight from global (fully coalesced,
// L2-resident after first c). Each thread produces 16 u outputs for its (b,n)
// as 8 packed f32x2 accumulators via FFMA2.
// ---------------------------------------------------------------------------
__global__ __launch_bounds__(256) void k1_uhat(const float* __restrict__ x,
                                               const float* __restrict__ W)
{
    __shared__ float Ws[32 * 132];
    const int n0 = blockIdx.x * 32;
    const int c  = blockIdx.y;
    const float* Wg = W + ((size_t)c * N_CAP + n0) * (DIN * U_SZ);

    // Stage W tile: 32 rows x 128 floats, contiguous in global.
    for (int idx = threadIdx.x; idx < 1024; idx += 256) {   // float4 count
        int n = idx >> 5, r = idx & 31;
        float4 v = ((const float4*)Wg)[(n << 5) + r];
        *(float4*)(Ws + n * 132 + (r << 2)) = v;
    }
    __syncthreads();

    const int bl = threadIdx.x & 7;    // b lane
    const int nl = threadIdx.x >> 3;   // n lane (0..31)
    const float* wrow = Ws + nl * 132;

    for (int bc = 0; bc < 32; ++bc) {
        const int b = (bc << 3) + bl;
        const float4* xp = (const float4*)(x + ((size_t)b * N_CAP + (n0 + nl)) * DIN);
        float4 xa = xp[0], xb = xp[1];
        float xi[8] = {xa.x, xa.y, xa.z, xa.w, xb.x, xb.y, xb.z, xb.w};

        unsigned long long acc[8];
        #pragma unroll
        for (int j = 0; j < 8; ++j) acc[j] = 0ull;   // bit pattern of (0f,0f)

        #pragma unroll
        for (int i = 0; i < 8; ++i) {
            unsigned long long xx;
            unsigned int xr = __float_as_uint(xi[i]);
            asm("mov.b64 %0, {%1, %1};" : "=l"(xx) : "r"(xr));
            const float* wr = wrow + (i << 4);
            #pragma unroll
            for (int q = 0; q < 4; ++q) {
                ulonglong2 wv = *(const ulonglong2*)(wr + (q << 2));
                FFMA2(acc[2 * q],     wv.x, xx, acc[2 * q]);
                FFMA2(acc[2 * q + 1], wv.y, xx, acc[2 * q + 1]);
            }
        }

        float* dst = g_uhat + (((size_t)b * C_SZ + c) * N_CAP + (n0 + nl)) * U_SZ;
        #pragma unroll
        for (int q = 0; q < 4; ++q) {
            ulonglong2 o; o.x = acc[2 * q]; o.y = acc[2 * q + 1];
            *(ulonglong2*)(dst + (q << 2)) = o;
        }
    }
}

// ---------------------------------------------------------------------------
// Block reductions (256 threads) using a 32-float scratch.
// ---------------------------------------------------------------------------
__device__ __forceinline__ float blockReduceSum(float v, float* scratch)
{
    #pragma unroll
    for (int o = 16; o > 0; o >>= 1) v += __shfl_xor_sync(0xffffffffu, v, o);
    if ((threadIdx.x & 31) == 0) scratch[threadIdx.x >> 5] = v;
    __syncthreads();
    float r = 0.f;
    #pragma unroll
    for (int i = 0; i < 8; ++i) r += scratch[i];
    __syncthreads();
    return r;
}

__device__ __forceinline__ float blockReduceMax(float v, float* scratch)
{
    #pragma unroll
    for (int o = 16; o > 0; o >>= 1) v = fmaxf(v, __shfl_xor_sync(0xffffffffu, v, o));
    if ((threadIdx.x & 31) == 0) scratch[threadIdx.x >> 5] = v;
    __syncthreads();
    float r = -3.0e38f;
    #pragma unroll
    for (int i = 0; i < 8; ++i) r = fmaxf(r, scratch[i]);
    __syncthreads();
    return r;
}

// ---------------------------------------------------------------------------
// K2: dynamic routing per (b,c). Grid (C, B), 256 threads.
// u_hat slice (1152x16 fp32) loaded once into smem (rows padded to 18 floats),
// then 3 routing iterations entirely from smem.
//   s-phase: thread = (u-pair p = tid&7, n-group g = tid>>3), conflict-free
//            float2 reads; cross-group reduce via 2 shfls + 8x16 smem tile.
//   softmax: per-n ownership (n = tid + 256k); normalization folded into s.
//   agreement: per-n ownership, exclusive b_logit update (no shfl/atomic).
// ---------------------------------------------------------------------------
__global__ __launch_bounds__(256) void k2_route(float* __restrict__ outp)
{
    extern __shared__ float sm[];
    float* uh    = sm;                     // N_CAP * ROW = 20736
    float* b_log = sm + N_CAP * ROW;       // 1152
    float* c_arr = b_log + N_CAP;          // 1152 (unnormalized exp weights)
    float* red   = c_arr + N_CAP;          // 128 (8 warps x 16 u)
    float* out_s = red + 128;              // 16
    float* red2  = out_s + 16;             // 32

    const int tid = threadIdx.x;
    const int c   = blockIdx.x;
    const int b   = blockIdx.y;

    // Load u_hat slice (contiguous 73.7KB) into padded smem rows.
    const float4* src = (const float4*)(g_uhat + ((size_t)b * C_SZ + c) * (N_CAP * U_SZ));
    for (int idx = tid; idx < (N_CAP * U_SZ) / 4; idx += 256) {
        float4 v = src[idx];
        int n = idx >> 2, q = idx & 3;
        float* d = uh + n * ROW + (q << 2);
        *(float2*)(d)     = make_float2(v.x, v.y);
        *(float2*)(d + 2) = make_float2(v.z, v.w);
    }
    for (int n = tid; n < N_CAP; n += 256) b_log[n] = 0.0f;  // softmax-shift invariant
    __syncthreads();

    const int p    = tid & 7;    // u-pair
    const int g    = tid >> 3;   // n-group (0..31)
    const int lane = tid & 31;
    const int w    = tid >> 5;

    for (int it = 0; it < 3; ++it) {
        float wsum_inv;
        if (it == 0) {
            wsum_inv = 1.0f / (float)N_CAP;   // softmax(const) is exactly uniform
        } else {
            float lm = -3.0e38f;
            for (int n = tid; n < N_CAP; n += 256) lm = fmaxf(lm, b_log[n]);
            float m = blockReduceMax(lm, red2);
            float ls = 0.0f;
            for (int n = tid; n < N_CAP; n += 256) {
                float e = expf(b_log[n] - m);
                c_arr[n] = e;
                ls += e;
            }
            float s = blockReduceSum(ls, red2);   // syncs make c_arr visible
            wsum_inv = 1.0f / s;
        }

        // ---- s[u] = wsum_inv * sum_n w_n * u_hat[n,u] ----
        float sx = 0.f, sy = 0.f;
        if (it == 0) {
            for (int n = g; n < N_CAP; n += 32) {
                float2 v = *(const float2*)(uh + n * ROW + (p << 1));
                sx += v.x; sy += v.y;
            }
        } else {
            for (int n = g; n < N_CAP; n += 32) {
                float2 v = *(const float2*)(uh + n * ROW + (p << 1));
                float cn = c_arr[n];
                sx = fmaf(cn, v.x, sx);
                sy = fmaf(cn, v.y, sy);
            }
        }
        sx += __shfl_xor_sync(0xffffffffu, sx, 8);
        sx += __shfl_xor_sync(0xffffffffu, sx, 16);
        sy += __shfl_xor_sync(0xffffffffu, sy, 8);
        sy += __shfl_xor_sync(0xffffffffu, sy, 16);
        if (lane < 8) {
            red[w * 16 + (lane << 1)]     = sx;
            red[w * 16 + (lane << 1) + 1] = sy;
        }
        __syncthreads();

        // ---- final s reduce + squash (first 16 threads, u = tid) ----
        if (tid < 16) {
            float s_u = 0.f;
            #pragma unroll
            for (int ww = 0; ww < 8; ++ww) s_u += red[ww * 16 + tid];
            s_u *= wsum_inv;
            float sq = s_u * s_u;
            sq += __shfl_xor_sync(0x0000ffffu, sq, 1, 16);
            sq += __shfl_xor_sync(0x0000ffffu, sq, 2, 16);
            sq += __shfl_xor_sync(0x0000ffffu, sq, 4, 16);
            sq += __shfl_xor_sync(0x0000ffffu, sq, 8, 16);
            float scale = sq / ((1.0f + sq) * sqrtf(sq + 1e-9f));
            float o = scale * s_u;
            out_s[tid] = o;
            if (it == 2) outp[((size_t)b * C_SZ + c) * U_SZ + tid] = o;
        }
        __syncthreads();

        // ---- agreement: b_log[n] += u_hat[n,:] . out ----
        if (it < 2) {
            float2 o2[8];
            #pragma unroll
            for (int j = 0; j < 8; ++j) o2[j] = *(const float2*)(out_s + (j << 1));
            #pragma unroll
            for (int k = 0; k < 5; ++k) {
                int n = tid + (k << 8);
                if (n < N_CAP) {
                    const float2* r = (const float2*)(uh + n * ROW);
                    float dot = 0.f;
                    #pragma unroll
                    for (int j = 0; j < 8; ++j) {
                        float2 v = r[j];
                        dot = fmaf(v.x, o2[j].x, dot);
                        dot = fmaf(v.y, o2[j].y, dot);
                    }
                    b_log[n] += dot;
                }
            }
            __syncthreads();
        }
    }
}

// ---------------------------------------------------------------------------
extern "C" void kernel_launch(void* const* d_in, const int* in_sizes, int n_in,
                              void* d_out, int out_size)
{
    const float* x = (const float*)d_in[0];
    const float* W = (const float*)d_in[1];
    // Robustness: identify tensors by element count in case of ordering swap.
    if (n_in >= 2 && in_sizes[0] == C_SZ * N_CAP * DIN * U_SZ &&
        in_sizes[1] == B_SZ * N_CAP * DIN) {
        const float* t = x; x = W; W = t;
    }

    const size_t smem2 =
        (size_t)(N_CAP * ROW + N_CAP + N_CAP + 128 + 16 + 32) * sizeof(float); // 92,864 B
    cudaFuncSetAttribute(k2_route, cudaFuncAttributeMaxDynamicSharedMemorySize,
                         (int)smem2);

    k1_uhat<<<dim3(N_CAP / 32, C_SZ), 256>>>(x, W);
    k2_route<<<dim3(C_SZ, B_SZ), 256, smem2>>>((float*)d_out);
}

// round 2
// speedup vs baseline: 2.2213x; 2.2213x over previous
#include <cuda_runtime.h>
#include <cuda_fp16.h>
#include <cstdint>
#include <cstddef>

#define B_SZ  256
#define C_SZ  10
#define N_CAP 1152
#define DIN   8
#define U_SZ  16
#define ROW   9     // half2-words per u_hat row in K2 smem (36B, conflict-light)

// 94.4 MB fp16 scratch for u_hat[b][c][n][u], stored as half2 words (u-pairs).
__device__ unsigned int g_uhat_h[(size_t)B_SZ * C_SZ * N_CAP * (U_SZ / 2)];

// Packed fp32x2 ops (sm_100+)
#define FFMA2(d, a, bb, cc) \
    asm("fma.rn.f32x2 %0, %1, %2, %3;" : "=l"(d) : "l"(a), "l"(bb), "l"(cc))
#define FADD2(d, a, bb) \
    asm("add.rn.f32x2 %0, %1, %2;" : "=l"(d) : "l"(a), "l"(bb))

// ---------------------------------------------------------------------------
// K1: u_hat[b,c,n,u] = sum_i x[b,n,i] * W[c,n,i,u]   (fp16 out)
// Grid (36, 10, 8): 32 n x one c x 32 b per block. 256 threads:
//   up = tid&7 (u-pair 0..7), nl = tid>>3 (n 0..31).
// Each thread holds W[c, n0+nl, :, 2up:2up+2] (8 f32x2) in REGISTERS,
// loops over 32 b reading x from smem (pre-duplicated f32x2, broadcast LDS).
// Warp store per b = 128B fully coalesced (4n x 8 u-pairs x 4B contiguous).
// ---------------------------------------------------------------------------
__global__ __launch_bounds__(256) void k1_uhat(const float* __restrict__ x,
                                               const float* __restrict__ W)
{
    __shared__ unsigned long long xsd[32 * 256];  // [b][n*8+i] dup'd x, 64KB

    const int n0 = blockIdx.x * 32;
    const int c  = blockIdx.y;
    const int b0 = blockIdx.z * 32;

    // Stage x for 32 b's, duplicating each scalar into an f32x2 pair.
    for (int t = threadIdx.x; t < 2048; t += 256) {     // 2048 float4 reads
        const int b = t >> 6, r = t & 63;               // r: float4 idx in b-row
        float4 v = ((const float4*)(x + ((size_t)(b0 + b) * N_CAP + n0) * DIN))[r];
        unsigned long long d0, d1, d2, d3;
        unsigned int u0 = __float_as_uint(v.x), u1 = __float_as_uint(v.y);
        unsigned int u2 = __float_as_uint(v.z), u3 = __float_as_uint(v.w);
        asm("mov.b64 %0, {%1, %1};" : "=l"(d0) : "r"(u0));
        asm("mov.b64 %0, {%1, %1};" : "=l"(d1) : "r"(u1));
        asm("mov.b64 %0, {%1, %1};" : "=l"(d2) : "r"(u2));
        asm("mov.b64 %0, {%1, %1};" : "=l"(d3) : "r"(u3));
        unsigned long long* dst = xsd + b * 256 + r * 4;
        ulonglong2 p0; p0.x = d0; p0.y = d1;
        ulonglong2 p1; p1.x = d2; p1.y = d3;
        *(ulonglong2*)(dst)     = p0;
        *(ulonglong2*)(dst + 2) = p1;
    }

    const int up = threadIdx.x & 7;
    const int nl = threadIdx.x >> 3;
    const int n  = n0 + nl;

    // W slice into registers: 8 i x (2 u) as f32x2. 8B loads, warp-coalesced.
    unsigned long long wr[8];
    const float* Wp = W + (((size_t)c * N_CAP + n) * DIN) * U_SZ + up * 2;
    #pragma unroll
    for (int i = 0; i < 8; ++i)
        wr[i] = *(const unsigned long long*)(Wp + i * U_SZ);

    __syncthreads();

    unsigned int* outp = g_uhat_h + ((size_t)(b0)*C_SZ + c) * (N_CAP * 8)
                                  + n * 8 + up;
    const unsigned long long* xrow = xsd + nl * 8;

    for (int b = 0; b < 32; ++b) {
        const unsigned long long* xp = xrow + b * 256;
        ulonglong2 xa = *(const ulonglong2*)(xp);
        ulonglong2 xb = *(const ulonglong2*)(xp + 2);
        ulonglong2 xc = *(const ulonglong2*)(xp + 4);
        ulonglong2 xd = *(const ulonglong2*)(xp + 6);

        unsigned long long a0 = 0ull, a1 = 0ull;
        FFMA2(a0, wr[0], xa.x, a0);  FFMA2(a1, wr[1], xa.y, a1);
        FFMA2(a0, wr[2], xb.x, a0);  FFMA2(a1, wr[3], xb.y, a1);
        FFMA2(a0, wr[4], xc.x, a0);  FFMA2(a1, wr[5], xc.y, a1);
        FFMA2(a0, wr[6], xd.x, a0);  FFMA2(a1, wr[7], xd.y, a1);
        FADD2(a0, a0, a1);

        unsigned int lo, hi;
        asm("mov.b64 {%0, %1}, %2;" : "=r"(lo), "=r"(hi) : "l"(a0));
        __half2 h = __floats2half2_rn(__uint_as_float(lo), __uint_as_float(hi));
        outp[(size_t)b * (C_SZ * N_CAP * 8)] = *(unsigned int*)&h;
    }
}

// ---------------------------------------------------------------------------
// Block reductions (256 threads / 8 warps)
// ---------------------------------------------------------------------------
__device__ __forceinline__ float blockReduceSum(float v, float* scratch)
{
    #pragma unroll
    for (int o = 16; o > 0; o >>= 1) v += __shfl_xor_sync(0xffffffffu, v, o);
    if ((threadIdx.x & 31) == 0) scratch[threadIdx.x >> 5] = v;
    __syncthreads();
    float r = 0.f;
    #pragma unroll
    for (int i = 0; i < 8; ++i) r += scratch[i];
    __syncthreads();
    return r;
}

__device__ __forceinline__ float blockReduceMax(float v, float* scratch)
{
    #pragma unroll
    for (int o = 16; o > 0; o >>= 1) v = fmaxf(v, __shfl_xor_sync(0xffffffffu, v, o));
    if ((threadIdx.x & 31) == 0) scratch[threadIdx.x >> 5] = v;
    __syncthreads();
    float r = -3.0e38f;
    #pragma unroll
    for (int i = 0; i < 8; ++i) r = fmaxf(r, scratch[i]);
    __syncthreads();
    return r;
}

// ---------------------------------------------------------------------------
// K2: dynamic routing per (b,c). Grid (C, B), 256 threads, ~51KB smem
// (4 CTAs/SM). u_hat slice loaded once as fp16 (36.9KB global, mostly L2),
// 3 routing iterations from smem.
// ---------------------------------------------------------------------------
__global__ __launch_bounds__(256) void k2_route(float* __restrict__ outp)
{
    extern __shared__ float sm[];
    unsigned int* uh = (unsigned int*)sm;          // N_CAP * ROW half2-words
    float* b_log = sm + N_CAP * ROW;               // 1152
    float* c_arr = b_log + N_CAP;                  // 1152
    float* red   = c_arr + N_CAP;                  // 128
    float* out_s = red + 128;                      // 16
    float* red2  = out_s + 16;                     // 32

    const int tid = threadIdx.x;
    const int c   = blockIdx.x;
    const int b   = blockIdx.y;

    // Load fp16 u_hat slice: 2304 uint4 (16B = 4 half2 words each).
    const uint4* src = (const uint4*)(g_uhat_h + ((size_t)b * C_SZ + c) * (N_CAP * 8));
    for (int idx = tid; idx < N_CAP * 2; idx += 256) {
        uint4 v = src[idx];
        const int n = idx >> 1, h = idx & 1;
        unsigned int* d = uh + n * ROW + h * 4;
        d[0] = v.x; d[1] = v.y; d[2] = v.z; d[3] = v.w;
    }
    for (int n = tid; n < N_CAP; n += 256) b_log[n] = 0.0f;
    __syncthreads();

    const int p    = tid & 7;    // u-pair
    const int g    = tid >> 3;   // n-group (0..31)
    const int lane = tid & 31;
    const int w    = tid >> 5;

    for (int it = 0; it < 3; ++it) {
        float wsum_inv;
        if (it == 0) {
            wsum_inv = 1.0f / (float)N_CAP;   // softmax(const) is uniform
        } else {
            float lm = -3.0e38f;
            for (int n = tid; n < N_CAP; n += 256) lm = fmaxf(lm, b_log[n]);
            float m = blockReduceMax(lm, red2);
            float ls = 0.0f;
            for (int n = tid; n < N_CAP; n += 256) {
                float e = __expf(b_log[n] - m);
                c_arr[n] = e;
                ls += e;
            }
            float s = blockReduceSum(ls, red2);
            wsum_inv = 1.0f / s;
        }

        // ---- s[u] partial sums ----
        float sx = 0.f, sy = 0.f;
        if (it == 0) {
            for (int n = g; n < N_CAP; n += 32) {
                __half2 hv = *(const __half2*)(uh + n * ROW + p);
                float2 v = __half22float2(hv);
                sx += v.x; sy += v.y;
            }
        } else {
            for (int n = g; n < N_CAP; n += 32) {
                __half2 hv = *(const __half2*)(uh + n * ROW + p);
                float2 v = __half22float2(hv);
                float cn = c_arr[n];
                sx = fmaf(cn, v.x, sx);
                sy = fmaf(cn, v.y, sy);
            }
        }
        sx += __shfl_xor_sync(0xffffffffu, sx, 8);
        sx += __shfl_xor_sync(0xffffffffu, sx, 16);
        sy += __shfl_xor_sync(0xffffffffu, sy, 8);
        sy += __shfl_xor_sync(0xffffffffu, sy, 16);
        if (lane < 8) {
            red[w * 16 + (lane << 1)]     = sx;
            red[w * 16 + (lane << 1) + 1] = sy;
        }
        __syncthreads();

        // ---- final reduce + squash (u = tid, first 16 threads) ----
        if (tid < 16) {
            float s_u = 0.f;
            #pragma unroll
            for (int ww = 0; ww < 8; ++ww) s_u += red[ww * 16 + tid];
            s_u *= wsum_inv;
            float sq = s_u * s_u;
            sq += __shfl_xor_sync(0x0000ffffu, sq, 1, 16);
            sq += __shfl_xor_sync(0x0000ffffu, sq, 2, 16);
            sq += __shfl_xor_sync(0x0000ffffu, sq, 4, 16);
            sq += __shfl_xor_sync(0x0000ffffu, sq, 8, 16);
            float scale = sq / ((1.0f + sq) * sqrtf(sq + 1e-9f));
            float o = scale * s_u;
            out_s[tid] = o;
            if (it == 2) outp[((size_t)b * C_SZ + c) * U_SZ + tid] = o;
        }
        __syncthreads();

        // ---- agreement: b_log[n] += u_hat[n,:] . out  (exclusive n per thread,
        //      LDS.32 at 9n mod 32: conflict-free) ----
        if (it < 2) {
            float2 o2[8];
            #pragma unroll
            for (int j = 0; j < 8; ++j) o2[j] = *(const float2*)(out_s + (j << 1));
            #pragma unroll
            for (int k = 0; k < 5; ++k) {
                int n = tid + (k << 8);
                if (n < N_CAP) {
                    const unsigned int* r = uh + n * ROW;
                    float dot = 0.f;
                    #pragma unroll
                    for (int j = 0; j < 8; ++j) {
                        float2 v = __half22float2(*(const __half2*)(r + j));
                        dot = fmaf(v.x, o2[j].x, dot);
                        dot = fmaf(v.y, o2[j].y, dot);
                    }
                    b_log[n] += dot;
                }
            }
            __syncthreads();
        }
    }
}

// ---------------------------------------------------------------------------
extern "C" void kernel_launch(void* const* d_in, const int* in_sizes, int n_in,
                              void* d_out, int out_size)
{
    const float* x = (const float*)d_in[0];
    const float* W = (const float*)d_in[1];
    if (n_in >= 2 && in_sizes[0] == C_SZ * N_CAP * DIN * U_SZ &&
        in_sizes[1] == B_SZ * N_CAP * DIN) {
        const float* t = x; x = W; W = t;
    }

    const size_t smem2 =
        (size_t)(N_CAP * ROW + N_CAP + N_CAP + 128 + 16 + 32) * sizeof(float); // ~51.4KB
    cudaFuncSetAttribute(k2_route, cudaFuncAttributeMaxDynamicSharedMemorySize,
                         (int)smem2);

    k1_uhat<<<dim3(N_CAP / 32, C_SZ, B_SZ / 32), 256>>>(x, W);
    k2_route<<<dim3(C_SZ, B_SZ), 256, smem2>>>((float*)d_out);
}

// round 3
// speedup vs baseline: 3.2308x; 1.4544x over previous
#include <cuda_runtime.h>
#include <cuda_fp16.h>
#include <cstdint>
#include <cstddef>

#define B_SZ  256
#define C_SZ  10
#define N_CAP 1152
#define DIN   8
#define U_SZ  16

// 94.4 MB fp16 scratch for u_hat[b][c][n][u], stored as half2 words (u-pairs).
__device__ unsigned int g_uhat_h[(size_t)B_SZ * C_SZ * N_CAP * (U_SZ / 2)];

// Packed fp32x2 FMA (sm_100+)
#define FFMA2(d, a, bb, cc) \
    asm("fma.rn.f32x2 %0, %1, %2, %3;" : "=l"(d) : "l"(a), "l"(bb), "l"(cc))
#define DUP2(d, s) \
    asm("mov.b64 %0, {%1, %1};" : "=l"(d) : "r"(s))

// ---------------------------------------------------------------------------
// K1: u_hat[b,c,n,u] = sum_i x[b,n,i] * W[c,n,i,u]   (fp16 out)
// Grid (36, 10, 8). 256 threads = 2 b-lanes x 32 n x 4 u-quads.
// W slice (8 i x 4 u) lives in registers as 16 f32x2. x staged in smem
// NON-duplicated (rows padded to 12 words: 8 n-lanes hit distinct banks,
// 16B-aligned for LDS.128); per b-step: 2x LDS.128 + 8 dup-movs (ALU pipe)
// + 16 FFMA2 (FMA pipe) + STG.64 (warp store = 256B contiguous).
// ---------------------------------------------------------------------------
__global__ __launch_bounds__(256) void k1_uhat(const float* __restrict__ x,
                                               const float* __restrict__ W)
{
    __shared__ float xs[32 * 32 * 12];   // [b][n][12] = 48KB

    const int n0 = blockIdx.x * 32;
    const int c  = blockIdx.y;
    const int b0 = blockIdx.z * 32;

    // Stage x: 1024 (b,n) rows of 32B.
    for (int t = threadIdx.x; t < 1024; t += 256) {
        const int b = t >> 5, n = t & 31;
        const float4* g = (const float4*)(x + ((size_t)(b0 + b) * N_CAP + (n0 + n)) * DIN);
        float4 v0 = g[0], v1 = g[1];
        float* d = xs + (b * 32 + n) * 12;
        *(float4*)(d)     = v0;
        *(float4*)(d + 4) = v1;
    }

    const int uq = threadIdx.x & 3;
    const int nl = (threadIdx.x >> 2) & 31;
    const int bl = threadIdx.x >> 7;
    const int n  = n0 + nl;

    // W slice into registers: 8 i, 4 u => 16 f32x2 (8x LDG.128).
    unsigned long long wr[16];
    {
        const ulonglong2* Wp =
            (const ulonglong2*)(W + ((size_t)c * N_CAP + n) * 128);
        #pragma unroll
        for (int i = 0; i < 8; ++i) {
            ulonglong2 w = Wp[i * 4 + uq];
            wr[2 * i]     = w.x;
            wr[2 * i + 1] = w.y;
        }
    }
    __syncthreads();

    unsigned int* op = g_uhat_h +
        ((size_t)(b0 + bl * 16) * C_SZ + c) * (N_CAP * 8) + n * 8 + uq * 2;

    #pragma unroll 4
    for (int s = 0; s < 16; ++s) {
        const int b = bl * 16 + s;
        const float* xp = xs + (b * 32 + nl) * 12;
        float4 xa = *(const float4*)(xp);
        float4 xb = *(const float4*)(xp + 4);

        unsigned long long x0, x1, x2, x3, x4, x5, x6, x7;
        DUP2(x0, __float_as_uint(xa.x));  DUP2(x1, __float_as_uint(xa.y));
        DUP2(x2, __float_as_uint(xa.z));  DUP2(x3, __float_as_uint(xa.w));
        DUP2(x4, __float_as_uint(xb.x));  DUP2(x5, __float_as_uint(xb.y));
        DUP2(x6, __float_as_uint(xb.z));  DUP2(x7, __float_as_uint(xb.w));

        unsigned long long a0 = 0ull, a1 = 0ull;
        FFMA2(a0, wr[0],  x0, a0);  FFMA2(a1, wr[1],  x0, a1);
        FFMA2(a0, wr[2],  x1, a0);  FFMA2(a1, wr[3],  x1, a1);
        FFMA2(a0, wr[4],  x2, a0);  FFMA2(a1, wr[5],  x2, a1);
        FFMA2(a0, wr[6],  x3, a0);  FFMA2(a1, wr[7],  x3, a1);
        FFMA2(a0, wr[8],  x4, a0);  FFMA2(a1, wr[9],  x4, a1);
        FFMA2(a0, wr[10], x5, a0);  FFMA2(a1, wr[11], x5, a1);
        FFMA2(a0, wr[12], x6, a0);  FFMA2(a1, wr[13], x6, a1);
        FFMA2(a0, wr[14], x7, a0);  FFMA2(a1, wr[15], x7, a1);

        unsigned int l0, h0, l1, h1;
        asm("mov.b64 {%0, %1}, %2;" : "=r"(l0), "=r"(h0) : "l"(a0));
        asm("mov.b64 {%0, %1}, %2;" : "=r"(l1), "=r"(h1) : "l"(a1));
        __half2 p0 = __floats2half2_rn(__uint_as_float(l0), __uint_as_float(h0));
        __half2 p1 = __floats2half2_rn(__uint_as_float(l1), __uint_as_float(h1));
        uint2 st;
        st.x = *(unsigned int*)&p0;
        st.y = *(unsigned int*)&p1;
        *(uint2*)op = st;
        op += (size_t)C_SZ * N_CAP * 8;
    }
}

// ---------------------------------------------------------------------------
// Block reduce sum (256 threads / 8 warps)
// ---------------------------------------------------------------------------
__device__ __forceinline__ float blockReduceSum(float v, float* scratch)
{
    #pragma unroll
    for (int o = 16; o > 0; o >>= 1) v += __shfl_xor_sync(0xffffffffu, v, o);
    if ((threadIdx.x & 31) == 0) scratch[threadIdx.x >> 5] = v;
    __syncthreads();
    float r = 0.f;
    #pragma unroll
    for (int i = 0; i < 8; ++i) r += scratch[i];
    __syncthreads();
    return r;
}

// ---------------------------------------------------------------------------
// K2: dynamic routing per (b,c). Grid (C, B), 256 threads, 46.2KB smem
// (4 CTAs/SM). u_hat stored TRANSPOSED in smem: uh[p][n] (p = u-pair).
//  - s-phase: warp p owns u-pair p; LDS.128 = 4 n at once; scalar FMA.
//  - agreement+exp+sum fused into ONE n-scan (no max pass: softmax is
//    shift-invariant and logits are bounded ~O(1)).
// ---------------------------------------------------------------------------
__global__ __launch_bounds__(256) void k2_route(float* __restrict__ outp)
{
    extern __shared__ float sm[];
    unsigned int* uh = (unsigned int*)sm;          // 8 x 1152 half2-words
    float* b_log = sm + 8 * N_CAP;                 // 1152
    float* c_arr = b_log + N_CAP;                  // 1152
    float* red   = c_arr + N_CAP;                  // 16
    float* out_s = red + 16;                       // 16
    float* red2  = out_s + 16;                     // 8

    const int tid = threadIdx.x;
    const int c   = blockIdx.x;
    const int b   = blockIdx.y;

    // Load + transpose u_hat slice: thread owns n, reads 32B row, scatters
    // 8 STS.32 (consecutive-n lanes -> distinct banks, conflict-free).
    const uint4* src = (const uint4*)(g_uhat_h + ((size_t)b * C_SZ + c) * (N_CAP * 8));
    for (int n = tid; n < N_CAP; n += 256) {
        uint4 v0 = src[2 * n], v1 = src[2 * n + 1];
        uh[0 * N_CAP + n] = v0.x;  uh[1 * N_CAP + n] = v0.y;
        uh[2 * N_CAP + n] = v0.z;  uh[3 * N_CAP + n] = v0.w;
        uh[4 * N_CAP + n] = v1.x;  uh[5 * N_CAP + n] = v1.y;
        uh[6 * N_CAP + n] = v1.z;  uh[7 * N_CAP + n] = v1.w;
    }
    __syncthreads();

    const int p = tid >> 5;          // warp = u-pair
    const int g = tid & 31;
    const unsigned int* uhp = uh + p * N_CAP;

    for (int it = 0; it < 3; ++it) {
        float inv;
        if (it == 0) {
            inv = 1.0f / (float)N_CAP;          // softmax(const) is uniform
        } else {
            // Fused agreement + exp + partial sum (one pass over n).
            float o2[16];
            #pragma unroll
            for (int j = 0; j < 8; ++j) {
                float2 t = *(const float2*)(out_s + 2 * j);
                o2[2 * j] = t.x;  o2[2 * j + 1] = t.y;
            }
            float ls = 0.f;
            for (int n = tid; n < N_CAP; n += 256) {
                float dot = 0.f;
                #pragma unroll
                for (int j = 0; j < 8; ++j) {
                    float2 v = __half22float2(*(const __half2*)(uh + j * N_CAP + n));
                    dot = fmaf(v.x, o2[2 * j], dot);
                    dot = fmaf(v.y, o2[2 * j + 1], dot);
                }
                float bn = (it == 1) ? dot : (b_log[n] + dot);
                if (it == 1) b_log[n] = bn;
                float e = __expf(bn);
                c_arr[n] = e;
                ls += e;
            }
            float s = blockReduceSum(ls, red2);   // syncs publish c_arr too
            inv = 1.0f / s;
        }

        // ---- s-phase: warp p sums its u-pair over all n ----
        float sx = 0.f, sy = 0.f;
        if (it == 0) {
            #pragma unroll
            for (int k = 0; k < 9; ++k) {
                uint4 hv = *(const uint4*)(uhp + k * 128 + 4 * g);
                float2 v0 = __half22float2(*(const __half2*)&hv.x);
                float2 v1 = __half22float2(*(const __half2*)&hv.y);
                float2 v2 = __half22float2(*(const __half2*)&hv.z);
                float2 v3 = __half22float2(*(const __half2*)&hv.w);
                sx += (v0.x + v1.x) + (v2.x + v3.x);
                sy += (v0.y + v1.y) + (v2.y + v3.y);
            }
        } else {
            #pragma unroll
            for (int k = 0; k < 9; ++k) {
                uint4 hv = *(const uint4*)(uhp + k * 128 + 4 * g);
                float4 cv = *(const float4*)(c_arr + k * 128 + 4 * g);
                float2 v0 = __half22float2(*(const __half2*)&hv.x);
                float2 v1 = __half22float2(*(const __half2*)&hv.y);
                float2 v2 = __half22float2(*(const __half2*)&hv.z);
                float2 v3 = __half22float2(*(const __half2*)&hv.w);
                sx = fmaf(cv.x, v0.x, sx);  sy = fmaf(cv.x, v0.y, sy);
                sx = fmaf(cv.y, v1.x, sx);  sy = fmaf(cv.y, v1.y, sy);
                sx = fmaf(cv.z, v2.x, sx);  sy = fmaf(cv.z, v2.y, sy);
                sx = fmaf(cv.w, v3.x, sx);  sy = fmaf(cv.w, v3.y, sy);
            }
        }
        #pragma unroll
        for (int o = 16; o > 0; o >>= 1) {
            sx += __shfl_xor_sync(0xffffffffu, sx, o);
            sy += __shfl_xor_sync(0xffffffffu, sy, o);
        }
        if (g == 0) { red[2 * p] = sx; red[2 * p + 1] = sy; }
        __syncthreads();

        // ---- squash (u = tid, first 16 threads) ----
        if (tid < 16) {
            float s_u = red[tid] * inv;
            float sq = s_u * s_u;
            sq += __shfl_xor_sync(0x0000ffffu, sq, 1, 16);
            sq += __shfl_xor_sync(0x0000ffffu, sq, 2, 16);
            sq += __shfl_xor_sync(0x0000ffffu, sq, 4, 16);
            sq += __shfl_xor_sync(0x0000ffffu, sq, 8, 16);
            float scale = sq / ((1.0f + sq) * sqrtf(sq + 1e-9f));
            float o = scale * s_u;
            out_s[tid] = o;
            if (it == 2) outp[((size_t)b * C_SZ + c) * U_SZ + tid] = o;
        }
        __syncthreads();
    }
}

// ---------------------------------------------------------------------------
extern "C" void kernel_launch(void* const* d_in, const int* in_sizes, int n_in,
                              void* d_out, int out_size)
{
    const float* x = (const float*)d_in[0];
    const float* W = (const float*)d_in[1];
    if (n_in >= 2 && in_sizes[0] == C_SZ * N_CAP * DIN * U_SZ &&
        in_sizes[1] == B_SZ * N_CAP * DIN) {
        const float* t = x; x = W; W = t;
    }

    const size_t smem2 =
        (size_t)(8 * N_CAP + N_CAP + N_CAP + 16 + 16 + 8) * sizeof(float); // 46,240B
    cudaFuncSetAttribute(k2_route, cudaFuncAttributeMaxDynamicSharedMemorySize,
                         (int)smem2);

    k1_uhat<<<dim3(N_CAP / 32, C_SZ, B_SZ / 32), 256>>>(x, W);
    k2_route<<<dim3(C_SZ, B_SZ), 256, smem2>>>((float*)d_out);
}